// round 3
// baseline (speedup 1.0000x reference)
#include <cuda_runtime.h>
#include <cstdint>

#define NTH   512
#define KSEL  100
#define NBINS 4096
#define CAP   2048
#define NMAX  16384

// dynamic smem layout (bytes)
#define OFF_KEYS   0                         // ushort[NMAX] = 32768
#define OFF_HC     (OFF_KEYS + NMAX*2)       // hist[4096] (16KB)  ∪  cand[2048] (16KB)
#define OFF_PSUM   (OFF_HC + 16384)          // unsigned[512]
#define OFF_DATA   (OFF_PSUM + 2048)         // float[KSEL*16]
#define OFF_BOX    (OFF_DATA + KSEL*16*4)
#define OFF_VAL    (OFF_BOX + KSEL*4*4)
#define OFF_BEL    (OFF_VAL + KSEL*4)
#define OFF_AREA   (OFF_BEL + KSEL*4)
#define OFF_KEEP   (OFF_AREA + KSEL*4)
#define OFF_VLD    (OFF_KEEP + KSEL*4)
#define OFF_NK     (OFF_VLD + KSEL*4)
#define OFF_SUP    (OFF_NK + KSEL*4)         // unsigned[KSEL][4]
#define OFF_MISC   (OFF_SUP + KSEL*16)       // wball[4],wmax[4],wmaxi[4],vkball[4],km[4], T,cnt,anyVK,bi
#define SMEM_BYTES (OFF_MISC + 24*4)

__device__ __forceinline__ unsigned fkey(float f) {
    unsigned u = __float_as_uint(f);
    return (u & 0x80000000u) ? ~u : (u | 0x80000000u);
}

__global__ __launch_bounds__(NTH) void pp_kernel(
    const float* __restrict__ blk_logit,
    const float* __restrict__ lin_logit,
    const float* __restrict__ chr_logit,
    const float* __restrict__ blk_raw,
    const float* __restrict__ lin_raw,
    const float* __restrict__ chr_raw,
    const float* __restrict__ tsz,
    float* __restrict__ out,
    int B, int NB, int NL, int NC)
{
    const int b   = blockIdx.x;
    const int lvl = blockIdx.y;
    const int tid = threadIdx.x;
    const int wid = tid >> 5;
    const int lane = tid & 31;

    int N, PN = 0, ef = 1;
    const float *logit, *raw, *praw = nullptr;
    bool bez = false;
    if (lvl == 0)      { N = NB; logit = blk_logit; raw = blk_raw; }
    else if (lvl == 1) { N = NL; logit = lin_logit; raw = lin_raw; praw = blk_raw; PN = NB; ef = 4; }
    else               { N = NC; logit = chr_logit; raw = chr_raw; praw = lin_raw; PN = NL; ef = 1; bez = true; }

    extern __shared__ unsigned char smraw[];
    unsigned short* keys16 = (unsigned short*)(smraw + OFF_KEYS);
    unsigned* hist = (unsigned*)(smraw + OFF_HC);
    unsigned long long* cand = (unsigned long long*)(smraw + OFF_HC);
    unsigned* psum = (unsigned*)(smraw + OFF_PSUM);
    float* s_data = (float*)(smraw + OFF_DATA);
    float* s_box  = (float*)(smraw + OFF_BOX);
    float* s_val  = (float*)(smraw + OFF_VAL);
    float* s_bel  = (float*)(smraw + OFF_BEL);
    float* s_area = (float*)(smraw + OFF_AREA);
    int*   s_keep = (int*)(smraw + OFF_KEEP);
    int*   s_vld  = (int*)(smraw + OFF_VLD);
    int*   s_nk   = (int*)(smraw + OFF_NK);
    unsigned (*sup)[4] = (unsigned (*)[4])(smraw + OFF_SUP);
    unsigned* misc = (unsigned*)(smraw + OFF_MISC);
    unsigned* wball = misc;            // [4]
    float*    wmax  = (float*)(misc + 4);
    int*      wmaxi = (int*)(misc + 8);
    unsigned* vkball = misc + 12;
    unsigned* km     = misc + 16;
    int*      s_T    = (int*)(misc + 20);
    unsigned* s_cnt  = misc + 21;
    int*      s_anyVK = (int*)(misc + 22);
    int*      s_bi    = (int*)(misc + 23);

    for (int i = tid; i < NBINS; i += NTH) hist[i] = 0;
    if (tid == 0) *s_cnt = 0;
    __syncthreads();

    // ---- Pass 1: keys16 to smem + warp-aggregated 12-bit histogram ----
    const float4* lp4 = (const float4*)(logit + (size_t)b * N);
    const float*  lp  = logit + (size_t)b * N;
    const int n4 = N >> 2;
    for (int i = tid; i < n4; i += NTH) {
        float4 v = lp4[i];
        unsigned k0 = fkey(v.x), k1 = fkey(v.y), k2 = fkey(v.z), k3 = fkey(v.w);
        // pack top-16 bits of each key
        unsigned lo = (k0 >> 16) | (k1 & 0xffff0000u);
        unsigned hi = (k2 >> 16) | (k3 & 0xffff0000u);
        ((uint2*)keys16)[i] = make_uint2(lo, hi);
        unsigned bins[4] = { k0 >> 20, k1 >> 20, k2 >> 20, k3 >> 20 };
        #pragma unroll
        for (int q = 0; q < 4; ++q) {
            unsigned mmask = __match_any_sync(0xffffffffu, bins[q]);
            int leader = __ffs(mmask) - 1;
            if (lane == leader) atomicAdd(&hist[bins[q]], __popc(mmask));
        }
    }
    __syncthreads();

    // ---- Per-thread chunk sums (8 bins each) ----
    {
        unsigned s = 0;
        int base = tid * (NBINS / NTH);
        #pragma unroll
        for (int j = 0; j < NBINS / NTH; ++j) s += hist[base + j];
        psum[tid] = s;
    }
    __syncthreads();

    // ---- Warp 0: find largest bin T with count(bins >= T) >= KSEL ----
    if (tid < 32) {
        const unsigned FULL = 0xffffffffu;
        unsigned carry = 0;
        for (int g = 15; g >= 0; --g) {
            unsigned v = psum[g * 32 + lane];
            unsigned s = v;
            #pragma unroll
            for (int off = 1; off < 32; off <<= 1) {
                unsigned n = __shfl_down_sync(FULL, s, off);
                if (lane + off < 32) s += n;
            }
            unsigned gsum = __shfl_sync(FULL, s, 0);
            if (carry + gsum >= (unsigned)KSEL) {
                unsigned ball = __ballot_sync(FULL, carry + s >= (unsigned)KSEL);
                int hi = 31 - __clz(ball);
                unsigned s_hi = __shfl_sync(FULL, s, hi);
                unsigned v_hi = __shfl_sync(FULL, v, hi);
                if (lane == 0) {
                    unsigned above = carry + s_hi - v_hi;
                    int C = g * 32 + hi;
                    int T = C * 8;
                    for (int w = 7; w >= 0; --w) {
                        above += hist[C * 8 + w];
                        if (above >= (unsigned)KSEL) { T = C * 8 + w; break; }
                    }
                    *s_T = T;
                }
                break;
            }
            carry += gsum;
        }
    }
    __syncthreads();
    const unsigned T = (unsigned)*s_T;
    __syncthreads();   // hist dead from here; cand aliases it

    // ---- Collect candidates from keys16; full key via gather reload ----
    for (int i = tid; i < n4; i += NTH) {
        uint2 packed = ((const uint2*)keys16)[i];
        unsigned k16[4] = { packed.x & 0xffffu, packed.x >> 16,
                            packed.y & 0xffffu, packed.y >> 16 };
        #pragma unroll
        for (int q = 0; q < 4; ++q) {
            if ((k16[q] >> 4) >= T) {
                unsigned pos = atomicAdd(s_cnt, 1u);
                if (pos < CAP) {
                    int idx = 4 * i + q;
                    unsigned fullk = fkey(lp[idx]);
                    cand[pos] = ((unsigned long long)fullk << 32) | (unsigned)(~idx);
                }
            }
        }
    }
    __syncthreads();
    int cnt = (int)*s_cnt; if (cnt > CAP) cnt = CAP;
    int P = 128; while (P < cnt) P <<= 1;
    for (int i = tid; i < P; i += NTH) if (i >= cnt) cand[i] = 0ULL;
    __syncthreads();

    // ---- Bitonic sort descending (composite = (key, ~idx): stable) ----
    for (int k = 2; k <= P; k <<= 1) {
        for (int j = k >> 1; j > 0; j >>= 1) {
            for (int i = tid; i < P; i += NTH) {
                int ixj = i ^ j;
                if (ixj > i) {
                    unsigned long long a = cand[i], c2 = cand[ixj];
                    bool desc = ((i & k) == 0);
                    if (desc ? (a < c2) : (a > c2)) { cand[i] = c2; cand[ixj] = a; }
                }
            }
            __syncthreads();
        }
    }

    const float ih = tsz[2 * b + 0];
    const float iw = tsz[2 * b + 1];

    // ---- Per-row decode ----
    if (tid < KSEL) {
        unsigned long long e = cand[tid];
        unsigned key = (unsigned)(e >> 32);
        int idx = (int)(~((unsigned)e));
        unsigned u = (key & 0x80000000u) ? (key ^ 0x80000000u) : ~key;
        float lg = __uint_as_float(u);
        float prob = 1.0f / (1.0f + expf(-lg));
        s_val[tid] = prob;
        s_keep[tid] = prob > 0.1f;

        float bx0, bx1, bx2, bx3;
        if (!bez) {
            const float* rp = raw + ((size_t)b * N + idx) * 4;
            float cx = rp[0], cy = rp[1], bw = rp[2], bh = rp[3];
            bx0 = (cx - 0.5f * bw) * iw;
            bx1 = (cy - 0.5f * bh) * ih;
            bx2 = (cx + 0.5f * bw) * iw;
            bx3 = (cy + 0.5f * bh) * ih;
            if (lvl == 0) {
                bx0 = fminf(fmaxf(bx0, 0.f), iw);
                bx1 = fminf(fmaxf(bx1, 0.f), ih);
                bx2 = fminf(fmaxf(bx2, 0.f), iw);
                bx3 = fminf(fmaxf(bx3, 0.f), ih);
            }
            s_data[tid * 16 + 0] = bx0; s_data[tid * 16 + 1] = bx1;
            s_data[tid * 16 + 2] = bx2; s_data[tid * 16 + 3] = bx3;
        } else {
            const float* rp = raw + ((size_t)b * N + idx) * 16;
            float cpt[16];
            #pragma unroll
            for (int q = 0; q < 8; ++q) {
                cpt[2 * q + 0] = rp[2 * q + 0] * ih;
                cpt[2 * q + 1] = rp[2 * q + 1] * iw;
            }
            #pragma unroll
            for (int q = 0; q < 16; ++q) s_data[tid * 16 + q] = cpt[q];
            float mn0 = 1e30f, mn1 = 1e30f, mx0 = -1e30f, mx1 = -1e30f;
            #pragma unroll
            for (int s2 = 0; s2 < 10; ++s2) {
                float t  = (float)s2 / 9.0f;
                float ti = 1.0f - t;
                float b0 = ti * ti * ti, b1 = 3.f * t * ti * ti;
                float b2 = 3.f * t * t * ti, b3 = t * t * t;
                float p0 = b0 * cpt[0] + b1 * cpt[2] + b2 * cpt[4]  + b3 * cpt[6];
                float p1 = b0 * cpt[1] + b1 * cpt[3] + b2 * cpt[5]  + b3 * cpt[7];
                float q0 = b0 * cpt[8] + b1 * cpt[10] + b2 * cpt[12] + b3 * cpt[14];
                float q1 = b0 * cpt[9] + b1 * cpt[11] + b2 * cpt[13] + b3 * cpt[15];
                mn0 = fminf(mn0, fminf(p0, q0));
                mn1 = fminf(mn1, fminf(p1, q1));
                mx0 = fmaxf(mx0, fmaxf(p0, q0));
                mx1 = fmaxf(mx1, fmaxf(p1, q1));
            }
            bx0 = mn0; bx1 = mn1; bx2 = mx0; bx3 = mx1;
        }
        s_box[tid * 4 + 0] = bx0; s_box[tid * 4 + 1] = bx1;
        s_box[tid * 4 + 2] = bx2; s_box[tid * 4 + 3] = bx3;
        float area = (bx2 - bx0) * (bx3 - bx1);
        s_area[tid] = area;

        if (lvl > 0) {
            const float* pr = praw + ((size_t)b * PN + idx / ef) * 4;
            float pcx = pr[0], pcy = pr[1], pw = pr[2], ph = pr[3];
            float px0 = (pcx - 0.5f * pw) * iw, py0 = (pcy - 0.5f * ph) * ih;
            float px1 = (pcx + 0.5f * pw) * iw, py1 = (pcy + 0.5f * ph) * ih;
            float ix1 = fmaxf(bx0, px0), iy1 = fmaxf(bx1, py0);
            float ix2 = fminf(bx2, px1), iy2 = fminf(bx3, py1);
            float inter = fmaxf(ix2 - ix1, 0.f) * fmaxf(iy2 - iy1, 0.f);
            float belong = inter / (area + 1e-6f);
            s_bel[tid] = belong;
            s_vld[tid] = belong > 0.6f;
        }
    }
    __syncthreads();

    // ---- keep.any() fallback via ballots ----
    if (tid < 128) {
        bool kp = (tid < KSEL) && (s_keep[tid] != 0);
        unsigned bal = __ballot_sync(0xffffffffu, kp);
        if (lane == 0) wball[wid] = bal;
    }
    __syncthreads();
    if (tid == 0) {
        unsigned any = wball[0] | wball[1] | wball[2] | wball[3];
        if (!any) s_keep[0] = 1;
    }
    __syncthreads();

    // ---- belong-valid fallback (argmax) via warp reduce ----
    if (lvl > 0) {
        if (tid < 128) {
            bool kp = (tid < KSEL) && (s_keep[tid] != 0);
            float v = kp ? s_bel[tid] : -3.0e38f;
            int   ix = tid;
            #pragma unroll
            for (int off = 16; off > 0; off >>= 1) {
                float ov = __shfl_down_sync(0xffffffffu, v, off);
                int   oi = __shfl_down_sync(0xffffffffu, ix, off);
                if (ov > v || (ov == v && oi < ix)) { v = ov; ix = oi; }
            }
            unsigned vk = __ballot_sync(0xffffffffu, kp && (tid < KSEL) && (s_vld[tid] != 0));
            if (lane == 0) { wmax[wid] = v; wmaxi[wid] = ix; vkball[wid] = vk; }
        }
        __syncthreads();
        if (tid == 0) {
            float bv = wmax[0]; int bidx = wmaxi[0];
            #pragma unroll
            for (int w = 1; w < 4; ++w)
                if (wmax[w] > bv) { bv = wmax[w]; bidx = wmaxi[w]; }
            *s_anyVK = (vkball[0] | vkball[1] | vkball[2] | vkball[3]) != 0;
            *s_bi = bidx;
        }
        __syncthreads();
    }
    if (tid < KSEL) {
        bool kp = s_keep[tid] != 0;
        int m;
        if (lvl > 0) m = *s_anyVK ? (kp && s_vld[tid]) : (kp && (tid == *s_bi));
        else m = kp;
        s_nk[tid] = m;
    }

    // ---- NMS: parallel suppression matrix ----
    __syncthreads();
    if (tid < KSEL) {
        float ax0 = s_box[tid * 4 + 0], ay0 = s_box[tid * 4 + 1];
        float ax1 = s_box[tid * 4 + 2], ay1 = s_box[tid * 4 + 3];
        float aa = s_area[tid];
        unsigned m0 = 0, m1 = 0, m2 = 0, m3 = 0;
        for (int j = tid + 1; j < KSEL; ++j) {
            float bx0 = s_box[j * 4 + 0], by0 = s_box[j * 4 + 1];
            float bx1 = s_box[j * 4 + 2], by1 = s_box[j * 4 + 3];
            float ix0 = fmaxf(ax0, bx0), iy0 = fmaxf(ay0, by0);
            float ix1 = fminf(ax1, bx1), iy1 = fminf(ay1, by1);
            float inter = fmaxf(ix1 - ix0, 0.f) * fmaxf(iy1 - iy0, 0.f);
            float iou = inter / (aa + s_area[j] - inter);
            if (iou > 0.1f) {
                unsigned bit = 1u << (j & 31);
                int w = j >> 5;
                if (w == 0) m0 |= bit; else if (w == 1) m1 |= bit;
                else if (w == 2) m2 |= bit; else m3 |= bit;
            }
        }
        sup[tid][0] = m0; sup[tid][1] = m1;
        sup[tid][2] = m2; sup[tid][3] = m3;
    }
    if (tid < 128) {
        unsigned bal = __ballot_sync(0xffffffffu, (tid < KSEL) && s_nk[tid]);
        if (lane == 0) km[wid] = bal;
    }
    __syncthreads();

    // ---- Single-thread bitmask greedy scan (no barriers) ----
    if (tid == 0) {
        unsigned k0 = km[0], k1 = km[1], k2 = km[2], k3 = km[3];
        for (int i = 0; i < KSEL; ++i) {
            unsigned word = (i < 32) ? k0 : (i < 64) ? k1 : (i < 96) ? k2 : k3;
            if ((word >> (i & 31)) & 1u) {
                k0 &= ~sup[i][0];
                k1 &= ~sup[i][1];
                k2 &= ~sup[i][2];
                k3 &= ~sup[i][3];
            }
        }
        km[0] = k0; km[1] = k1; km[2] = k2; km[3] = k3;
    }
    __syncthreads();

    // ---- Write outputs ----
    size_t nbd = (size_t)B * 400;
    size_t nsc = (size_t)B * 100;
    size_t oD, oS, oK;
    if (lvl == 0)      { oD = 0; oS = nbd; oK = nbd + nsc; }
    else if (lvl == 1) { size_t base = nbd + 2 * nsc; oD = base; oS = base + nbd; oK = oS + nsc; }
    else               { size_t base = 2 * (nbd + 2 * nsc); oD = base; oS = base + (size_t)B * 1600; oK = oS + nsc; }

    if (tid < KSEL) {
        bool nk = (km[tid >> 5] >> (tid & 31)) & 1u;
        out[oS + (size_t)b * 100 + tid] = nk ? s_val[tid] : 0.f;
        out[oK + (size_t)b * 100 + tid] = nk ? 1.f : 0.f;
        int D = bez ? 16 : 4;
        float* dp = out + oD + ((size_t)b * 100 + tid) * D;
        for (int d2 = 0; d2 < D; ++d2) dp[d2] = nk ? s_data[tid * 16 + d2] : 0.f;
    }
}

extern "C" void kernel_launch(void* const* d_in, const int* in_sizes, int n_in,
                              void* d_out, int out_size) {
    const float* blk_logit = (const float*)d_in[0];
    const float* lin_logit = (const float*)d_in[1];
    const float* chr_logit = (const float*)d_in[2];
    const float* blk_raw   = (const float*)d_in[3];
    const float* lin_raw   = (const float*)d_in[4];
    const float* chr_raw   = (const float*)d_in[5];
    const float* tsz       = (const float*)d_in[6];
    float* out = (float*)d_out;

    int B  = in_sizes[6] / 2;
    int NB = in_sizes[0] / B;
    int NL = in_sizes[1] / B;
    int NC = in_sizes[2] / B;

    cudaFuncSetAttribute(pp_kernel, cudaFuncAttributeMaxDynamicSharedMemorySize, SMEM_BYTES);
    dim3 grid(B, 3);
    pp_kernel<<<grid, NTH, SMEM_BYTES>>>(blk_logit, lin_logit, chr_logit,
                                         blk_raw, lin_raw, chr_raw, tsz, out,
                                         B, NB, NL, NC);
}

// round 4
// speedup vs baseline: 2.5310x; 2.5310x over previous
#include <cuda_runtime.h>
#include <cstdint>

#define NTH   512
#define KSEL  100
#define NBINS 4096
#define CAP   2048

// smem layout sizes
#define SM_CAND   (CAP * 8)            // 16384
#define SM_KEYS   (16384 * 4)          // 65536
#define SM_HIST   (NBINS * 4)          // 16384
#define SM_ROWS   (KSEL*16*4 + KSEL*4*4 + 7*KSEL*4 + 32)
#define SMEM_BYTES (SM_CAND + SM_KEYS + SM_HIST + SM_ROWS)

__global__ __launch_bounds__(NTH) void pp_kernel(
    const float* __restrict__ blk_logit,
    const float* __restrict__ lin_logit,
    const float* __restrict__ chr_logit,
    const float* __restrict__ blk_raw,
    const float* __restrict__ lin_raw,
    const float* __restrict__ chr_raw,
    const float* __restrict__ tsz,
    float* __restrict__ out,
    int B, int NB, int NL, int NC)
{
    // Tail-balanced remap: heavy CTAs (lvl1/lvl2) occupy block ids [0, 2B) so
    // they all land in wave 1; the light lvl0 CTAs fill the tail.
    const int bid = blockIdx.x;
    int b, lvl;
    if (bid < 2 * B) { lvl = 1 + (bid & 1); b = bid >> 1; }
    else             { lvl = 0; b = bid - 2 * B; }
    const int tid = threadIdx.x;

    int N, PN = 0, ef = 1;
    const float *logit, *raw, *praw = nullptr;
    bool bez = false;
    if (lvl == 0)      { N = NB; logit = blk_logit; raw = blk_raw; }
    else if (lvl == 1) { N = NL; logit = lin_logit; raw = lin_raw; praw = blk_raw; PN = NB; ef = 4; }
    else               { N = NC; logit = chr_logit; raw = chr_raw; praw = lin_raw; PN = NL; ef = 1; bez = true; }

    extern __shared__ unsigned char sm[];
    unsigned long long* cand = (unsigned long long*)sm;
    unsigned* keys = (unsigned*)(sm + SM_CAND);
    unsigned* hist = (unsigned*)(sm + SM_CAND + SM_KEYS);
    unsigned char* p = sm + SM_CAND + SM_KEYS + SM_HIST;
    float* s_data = (float*)p; p += KSEL * 16 * 4;
    float* s_box  = (float*)p; p += KSEL * 4 * 4;
    float* s_val  = (float*)p; p += KSEL * 4;
    float* s_bel  = (float*)p; p += KSEL * 4;
    float* s_area = (float*)p; p += KSEL * 4;
    int*   s_keep = (int*)p;   p += KSEL * 4;
    int*   s_vld  = (int*)p;   p += KSEL * 4;
    int*   s_nk   = (int*)p;   p += KSEL * 4;
    int*   s_T    = (int*)p;   p += 4;
    unsigned* s_cnt = (unsigned*)p;

    for (int i = tid; i < NBINS; i += NTH) hist[i] = 0;
    if (tid == 0) *s_cnt = 0;
    __syncthreads();

    // ---- Pass 1: monotonic keys + histogram of top 12 key bits ----
    const float* lp = logit + (size_t)b * N;
    for (int i = tid; i < N; i += NTH) {
        unsigned u = __float_as_uint(lp[i]);
        unsigned key = (u & 0x80000000u) ? ~u : (u | 0x80000000u);
        keys[i] = key;
        atomicAdd(&hist[key >> 20], 1u);
    }
    __syncthreads();

    // ---- Per-thread chunk sums (8 bins each), alias psum onto cand area ----
    unsigned* psum = (unsigned*)cand;
    {
        unsigned s = 0;
        int base = tid * (NBINS / NTH);
        #pragma unroll
        for (int j = 0; j < NBINS / NTH; ++j) s += hist[base + j];
        psum[tid] = s;
    }
    __syncthreads();

    // ---- Warp 0: find largest bin T with count(bins >= T) >= KSEL ----
    if (tid < 32) {
        const unsigned FULL = 0xffffffffu;
        int lane = tid;
        unsigned carry = 0;
        for (int g = 15; g >= 0; --g) {
            unsigned v = psum[g * 32 + lane];
            unsigned s = v;
            #pragma unroll
            for (int off = 1; off < 32; off <<= 1) {
                unsigned n = __shfl_down_sync(FULL, s, off);
                if (lane + off < 32) s += n;
            }
            unsigned gsum = __shfl_sync(FULL, s, 0);
            if (carry + gsum >= (unsigned)KSEL) {
                unsigned ball = __ballot_sync(FULL, carry + s >= (unsigned)KSEL);
                int hi = 31 - __clz(ball);
                unsigned s_hi = __shfl_sync(FULL, s, hi);
                unsigned v_hi = __shfl_sync(FULL, v, hi);
                if (lane == 0) {
                    unsigned above = carry + s_hi - v_hi;  // count of chunks > C
                    int C = g * 32 + hi;
                    int T = C * 8;
                    for (int w = 7; w >= 0; --w) {
                        above += hist[C * 8 + w];
                        if (above >= (unsigned)KSEL) { T = C * 8 + w; break; }
                    }
                    *s_T = T;
                }
                break;
            }
            carry += gsum;
        }
    }
    __syncthreads();
    const unsigned T = (unsigned)*s_T;

    // ---- Collect candidates with bin >= T ----
    for (int i = tid; i < N; i += NTH) {
        unsigned key = keys[i];
        if ((key >> 20) >= T) {
            unsigned pos = atomicAdd(s_cnt, 1u);
            if (pos < CAP)
                cand[pos] = ((unsigned long long)key << 32) | (unsigned)(~i);
        }
    }
    __syncthreads();
    int cnt = (int)*s_cnt; if (cnt > CAP) cnt = CAP;
    int P = 128; while (P < cnt) P <<= 1;
    for (int i = tid; i < P; i += NTH) if (i >= cnt) cand[i] = 0ULL;
    __syncthreads();

    // ---- Bitonic sort descending (composite = (key, ~idx): stable lower-index first) ----
    for (int k = 2; k <= P; k <<= 1) {
        for (int j = k >> 1; j > 0; j >>= 1) {
            for (int i = tid; i < P; i += NTH) {
                int ixj = i ^ j;
                if (ixj > i) {
                    unsigned long long a = cand[i], c2 = cand[ixj];
                    bool desc = ((i & k) == 0);
                    if (desc ? (a < c2) : (a > c2)) { cand[i] = c2; cand[ixj] = a; }
                }
            }
            __syncthreads();
        }
    }

    const float ih = tsz[2 * b + 0];  // target h
    const float iw = tsz[2 * b + 1];  // target w

    // ---- Per-row decode (one thread per selected row) ----
    if (tid < KSEL) {
        unsigned long long e = cand[tid];
        unsigned key = (unsigned)(e >> 32);
        int idx = (int)(~((unsigned)e));
        unsigned u = (key & 0x80000000u) ? (key ^ 0x80000000u) : ~key;
        float lg = __uint_as_float(u);
        float prob = 1.0f / (1.0f + expf(-lg));
        s_val[tid] = prob;
        s_keep[tid] = prob > 0.1f;

        float bx0, bx1, bx2, bx3;
        if (!bez) {
            const float* rp = raw + ((size_t)b * N + idx) * 4;
            float cx = rp[0], cy = rp[1], bw = rp[2], bh = rp[3];
            bx0 = (cx - 0.5f * bw) * iw;
            bx1 = (cy - 0.5f * bh) * ih;
            bx2 = (cx + 0.5f * bw) * iw;
            bx3 = (cy + 0.5f * bh) * ih;
            if (lvl == 0) {
                bx0 = fminf(fmaxf(bx0, 0.f), iw);
                bx1 = fminf(fmaxf(bx1, 0.f), ih);
                bx2 = fminf(fmaxf(bx2, 0.f), iw);
                bx3 = fminf(fmaxf(bx3, 0.f), ih);
            }
            s_data[tid * 16 + 0] = bx0; s_data[tid * 16 + 1] = bx1;
            s_data[tid * 16 + 2] = bx2; s_data[tid * 16 + 3] = bx3;
        } else {
            const float* rp = raw + ((size_t)b * N + idx) * 16;
            float cpt[16];
            #pragma unroll
            for (int q = 0; q < 8; ++q) {
                cpt[2 * q + 0] = rp[2 * q + 0] * ih;   // tile(tsize,8): even -> h
                cpt[2 * q + 1] = rp[2 * q + 1] * iw;   // odd -> w
            }
            #pragma unroll
            for (int q = 0; q < 16; ++q) s_data[tid * 16 + q] = cpt[q];
            float mn0 = 1e30f, mn1 = 1e30f, mx0 = -1e30f, mx1 = -1e30f;
            #pragma unroll
            for (int s2 = 0; s2 < 10; ++s2) {
                float t  = (float)s2 / 9.0f;
                float ti = 1.0f - t;
                float b0 = ti * ti * ti, b1 = 3.f * t * ti * ti;
                float b2 = 3.f * t * t * ti, b3 = t * t * t;
                float p0 = b0 * cpt[0] + b1 * cpt[2] + b2 * cpt[4]  + b3 * cpt[6];
                float p1 = b0 * cpt[1] + b1 * cpt[3] + b2 * cpt[5]  + b3 * cpt[7];
                float q0 = b0 * cpt[8] + b1 * cpt[10] + b2 * cpt[12] + b3 * cpt[14];
                float q1 = b0 * cpt[9] + b1 * cpt[11] + b2 * cpt[13] + b3 * cpt[15];
                mn0 = fminf(mn0, fminf(p0, q0));
                mn1 = fminf(mn1, fminf(p1, q1));
                mx0 = fmaxf(mx0, fmaxf(p0, q0));
                mx1 = fmaxf(mx1, fmaxf(p1, q1));
            }
            bx0 = mn0; bx1 = mn1; bx2 = mx0; bx3 = mx1;
        }
        s_box[tid * 4 + 0] = bx0; s_box[tid * 4 + 1] = bx1;
        s_box[tid * 4 + 2] = bx2; s_box[tid * 4 + 3] = bx3;
        float area = (bx2 - bx0) * (bx3 - bx1);
        s_area[tid] = area;

        if (lvl > 0) {
            const float* pr = praw + ((size_t)b * PN + idx / ef) * 4;
            float pcx = pr[0], pcy = pr[1], pw = pr[2], ph = pr[3];
            float px0 = (pcx - 0.5f * pw) * iw, py0 = (pcy - 0.5f * ph) * ih;
            float px1 = (pcx + 0.5f * pw) * iw, py1 = (pcy + 0.5f * ph) * ih;
            float ix1 = fmaxf(bx0, px0), iy1 = fmaxf(bx1, py0);
            float ix2 = fminf(bx2, px1), iy2 = fminf(bx3, py1);
            float inter = fmaxf(ix2 - ix1, 0.f) * fmaxf(iy2 - iy1, 0.f);
            float belong = inter / (area + 1e-6f);
            s_bel[tid] = belong;
            s_vld[tid] = belong > 0.6f;
        }
    }
    __syncthreads();

    // ---- Serial reductions: keep fallback, belong-valid fallback, init mask ----
    if (tid == 0) {
        bool any = false;
        for (int r = 0; r < KSEL; ++r) any = any || (s_keep[r] != 0);
        if (!any) s_keep[0] = 1;
        if (lvl > 0) {
            bool anyVK = false;
            float best = -1e38f; int bi = 0;
            for (int r = 0; r < KSEL; ++r) {
                bool kp = s_keep[r] != 0;
                if (kp && s_vld[r]) anyVK = true;
                float v2 = kp ? s_bel[r] : -1e38f;
                if (v2 > best) { best = v2; bi = r; }
            }
            for (int r = 0; r < KSEL; ++r) {
                int m = anyVK ? (s_keep[r] && s_vld[r])
                              : (s_keep[r] && (r == bi));
                s_nk[r] = m;
            }
        } else {
            for (int r = 0; r < KSEL; ++r) s_nk[r] = s_keep[r];
        }
    }

    // ---- Greedy NMS (sequential over i; columns parallel) ----
    for (int i = 0; i < KSEL - 1; ++i) {
        __syncthreads();
        if (tid > i && tid < KSEL && s_nk[i]) {
            float ax0 = s_box[i * 4 + 0], ay0 = s_box[i * 4 + 1];
            float ax1 = s_box[i * 4 + 2], ay1 = s_box[i * 4 + 3];
            float bx0 = s_box[tid * 4 + 0], by0 = s_box[tid * 4 + 1];
            float bx1 = s_box[tid * 4 + 2], by1 = s_box[tid * 4 + 3];
            float ix0 = fmaxf(ax0, bx0), iy0 = fmaxf(ay0, by0);
            float ix1 = fminf(ax1, bx1), iy1 = fminf(ay1, by1);
            float inter = fmaxf(ix1 - ix0, 0.f) * fmaxf(iy1 - iy0, 0.f);
            float iou = inter / (s_area[i] + s_area[tid] - inter);
            if (iou > 0.1f) s_nk[tid] = 0;
        }
    }
    __syncthreads();

    // ---- Write outputs (flattened tuple order: blk d/s/k, lin d/s/k, chr d/s/k) ----
    size_t nbd = (size_t)B * 400;   // B*100*4
    size_t nsc = (size_t)B * 100;
    size_t oD, oS, oK;
    if (lvl == 0)      { oD = 0; oS = nbd; oK = nbd + nsc; }
    else if (lvl == 1) { size_t base = nbd + 2 * nsc; oD = base; oS = base + nbd; oK = oS + nsc; }
    else               { size_t base = 2 * (nbd + 2 * nsc); oD = base; oS = base + (size_t)B * 1600; oK = oS + nsc; }

    if (tid < KSEL) {
        bool nk = s_nk[tid] != 0;
        out[oS + (size_t)b * 100 + tid] = nk ? s_val[tid] : 0.f;
        out[oK + (size_t)b * 100 + tid] = nk ? 1.f : 0.f;
        int D = bez ? 16 : 4;
        float* dp = out + oD + ((size_t)b * 100 + tid) * D;
        for (int d2 = 0; d2 < D; ++d2) dp[d2] = nk ? s_data[tid * 16 + d2] : 0.f;
    }
}

extern "C" void kernel_launch(void* const* d_in, const int* in_sizes, int n_in,
                              void* d_out, int out_size) {
    const float* blk_logit = (const float*)d_in[0];
    const float* lin_logit = (const float*)d_in[1];
    const float* chr_logit = (const float*)d_in[2];
    const float* blk_raw   = (const float*)d_in[3];
    const float* lin_raw   = (const float*)d_in[4];
    const float* chr_raw   = (const float*)d_in[5];
    const float* tsz       = (const float*)d_in[6];
    float* out = (float*)d_out;

    int B  = in_sizes[6] / 2;
    int NB = in_sizes[0] / B;
    int NL = in_sizes[1] / B;
    int NC = in_sizes[2] / B;

    cudaFuncSetAttribute(pp_kernel, cudaFuncAttributeMaxDynamicSharedMemorySize, SMEM_BYTES);
    pp_kernel<<<3 * B, NTH, SMEM_BYTES>>>(blk_logit, lin_logit, chr_logit,
                                          blk_raw, lin_raw, chr_raw, tsz, out,
                                          B, NB, NL, NC);
}